// round 1
// baseline (speedup 1.0000x reference)
#include <cuda_runtime.h>
#include <math.h>

// Problem constants
#define Bsz   4096
#define Hn    512
#define H3    1536
#define Ln    3
#define Tn    16
#define Cn    512
#define NSTEP 17          // 1 transition step + 16 scan steps

// ---------------- persistent device scratch (no allocations allowed) -------
__device__ float g_bufA[(size_t)NSTEP * Bsz * Hn];   // 142.6 MB  input/output seq ping
__device__ float g_bufB[(size_t)NSTEP * Bsz * Hn];   // 142.6 MB  input/output seq pong
__device__ float g_GI[(size_t)NSTEP * Bsz * H3];     // 427.8 MB  batched input gates
__device__ float g_GH[(size_t)Bsz * H3];             //  25.2 MB  per-step hidden gates

// ---------------------------------------------------------------------------
// Generic NT SGEMM: C[m,n] = sum_k A[m,k]*Bw[n,k] + bias[n]
// Both operands K-contiguous (row-major [M,K] and [N,K]).
// 128x128 block tile, BK=16, 256 threads, 8x8 per-thread microtile.
// MODE 0: plain A rows, plain row-major C (ld = N)
// MODE 1: A rows gathered through token table (tok-emb projection)
// MODE 2: plain A rows, C scattered to logits layout [B, T, C]
// ---------------------------------------------------------------------------
template <int MODE>
__global__ void __launch_bounds__(256)
sgemm_nt(const float* __restrict__ A, const float* __restrict__ Bw,
         const float* __restrict__ bias, float* __restrict__ C,
         int M, int N, int K, const int* __restrict__ gidx)
{
    __shared__ float As[16][132];
    __shared__ float Bs[16][132];

    const int m0  = blockIdx.y * 128;
    const int n0  = blockIdx.x * 128;
    const int tid = threadIdx.x;
    const int lr  = tid >> 2;          // 0..63  tile row for loads
    const int lk  = (tid & 3) << 2;    // 0,4,8,12 k-offset for loads
    const int tx  = tid & 15;          // microtile col group
    const int ty  = tid >> 4;          // microtile row group

    const float* Arow0;
    const float* Arow1;
    if (MODE == 1) {
        // m = s*B + b ; token index = gt[b*T + s]
        int ma0 = m0 + lr, ma1 = ma0 + 64;
        Arow0 = A + (size_t)gidx[(ma0 & (Bsz - 1)) * Tn + (ma0 >> 12)] * K;
        Arow1 = A + (size_t)gidx[(ma1 & (Bsz - 1)) * Tn + (ma1 >> 12)] * K;
    } else {
        Arow0 = A + (size_t)(m0 + lr) * K;
        Arow1 = Arow0 + (size_t)64 * K;
    }
    const float* Brow0 = Bw + (size_t)(n0 + lr) * K;
    const float* Brow1 = Brow0 + (size_t)64 * K;

    float acc[8][8];
#pragma unroll
    for (int i = 0; i < 8; i++)
#pragma unroll
        for (int j = 0; j < 8; j++) acc[i][j] = 0.f;

    for (int k0 = 0; k0 < K; k0 += 16) {
        float4 a0 = *(const float4*)(Arow0 + k0 + lk);
        float4 a1 = *(const float4*)(Arow1 + k0 + lk);
        float4 b0 = *(const float4*)(Brow0 + k0 + lk);
        float4 b1 = *(const float4*)(Brow1 + k0 + lk);
        __syncthreads();   // protect smem of previous iteration
        As[lk + 0][lr] = a0.x; As[lk + 1][lr] = a0.y; As[lk + 2][lr] = a0.z; As[lk + 3][lr] = a0.w;
        As[lk + 0][lr + 64] = a1.x; As[lk + 1][lr + 64] = a1.y; As[lk + 2][lr + 64] = a1.z; As[lk + 3][lr + 64] = a1.w;
        Bs[lk + 0][lr] = b0.x; Bs[lk + 1][lr] = b0.y; Bs[lk + 2][lr] = b0.z; Bs[lk + 3][lr] = b0.w;
        Bs[lk + 0][lr + 64] = b1.x; Bs[lk + 1][lr + 64] = b1.y; Bs[lk + 2][lr + 64] = b1.z; Bs[lk + 3][lr + 64] = b1.w;
        __syncthreads();
#pragma unroll
        for (int kk = 0; kk < 16; kk++) {
            float a[8], b[8];
#pragma unroll
            for (int i = 0; i < 8; i++) a[i] = As[kk][ty * 8 + i];
#pragma unroll
            for (int j = 0; j < 8; j++) b[j] = Bs[kk][tx * 8 + j];
#pragma unroll
            for (int i = 0; i < 8; i++)
#pragma unroll
                for (int j = 0; j < 8; j++)
                    acc[i][j] = fmaf(a[i], b[j], acc[i][j]);
        }
    }

    float bb[8];
#pragma unroll
    for (int j = 0; j < 8; j++) bb[j] = bias[n0 + tx * 8 + j];

#pragma unroll
    for (int i = 0; i < 8; i++) {
        int m = m0 + ty * 8 + i;
#pragma unroll
        for (int j = 0; j < 8; j += 4) {
            float4 v;
            v.x = acc[i][j + 0] + bb[j + 0];
            v.y = acc[i][j + 1] + bb[j + 1];
            v.z = acc[i][j + 2] + bb[j + 2];
            v.w = acc[i][j + 3] + bb[j + 3];
            size_t off;
            if (MODE == 2) {
                int b = m & (Bsz - 1), s = m >> 12;       // m = s*B + b
                off = (size_t)b * (Tn * Cn) + (size_t)s * Cn + n0 + tx * 8 + j;
            } else {
                off = (size_t)m * N + n0 + tx * 8 + j;
            }
            *(float4*)(C + off) = v;
        }
    }
}

// ---------------------------------------------------------------------------
__device__ __forceinline__ float sigmoidf_(float x) { return 1.f / (1.f + expf(-x)); }

// torch GRUCell gate math (order r,z,n) given precomputed gi (with b_ih) and
// gh (with b_hh). h' = (1-z)*n + z*h
__global__ void gru_gate_kernel(const float* __restrict__ GIt, const float* __restrict__ GH,
                                const float* __restrict__ hprev, float* __restrict__ hout)
{
    int i = blockIdx.x * blockDim.x + threadIdx.x;
    if (i >= Bsz * Hn) return;
    int b = i >> 9;
    int j = i & (Hn - 1);
    size_t o = (size_t)b * H3 + j;
    float r = sigmoidf_(GIt[o] + GH[o]);
    float z = sigmoidf_(GIt[o + 512] + GH[o + 512]);
    float n = tanhf(GIt[o + 1024] + r * GH[o + 1024]);
    hout[i] = (1.f - z) * n + z * hprev[i];
}

// x0 = action @ W_a.T + b_a  (A=3), plus zero-fill of sequence slot 1
__global__ void u0_kernel(const float* __restrict__ action, const float* __restrict__ W_a,
                          const float* __restrict__ b_a, float* __restrict__ U)
{
    int i = blockIdx.x * blockDim.x + threadIdx.x;
    if (i >= Bsz * Hn) return;
    int b = i >> 9, j = i & 511;
    float s = b_a[j];
    s = fmaf(action[b * 3 + 0], W_a[j * 3 + 0], s);
    s = fmaf(action[b * 3 + 1], W_a[j * 3 + 1], s);
    s = fmaf(action[b * 3 + 2], W_a[j * 3 + 2], s);
    U[i] = s;
    U[(size_t)Bsz * Hn + i] = 0.f;   // scan step 0 input is zeros
}

// reward / done heads from h_trans[-1] (one warp per batch row)
__global__ void heads_kernel(const float* __restrict__ h2, const float* __restrict__ W_r,
                             const float* __restrict__ b_r, const float* __restrict__ W_d,
                             const float* __restrict__ b_d,
                             float* __restrict__ outr, float* __restrict__ outd)
{
    int gw = (blockIdx.x * blockDim.x + threadIdx.x) >> 5;
    int lane = threadIdx.x & 31;
    if (gw >= Bsz) return;
    const float* hb = h2 + (size_t)gw * Hn;
    float sr = 0.f, sd = 0.f;
#pragma unroll
    for (int k = lane; k < Hn; k += 32) {
        float v = hb[k];
        sr = fmaf(v, W_r[k], sr);
        sd = fmaf(v, W_d[k], sd);
    }
#pragma unroll
    for (int o = 16; o > 0; o >>= 1) {
        sr += __shfl_down_sync(0xffffffffu, sr, o);
        sd += __shfl_down_sync(0xffffffffu, sd, o);
    }
    if (lane == 0) { outr[gw] = sr + b_r[0]; outd[gw] = sd + b_d[0]; }
}

__global__ void copy_kernel(const float* __restrict__ src, float* __restrict__ dst)
{
    int i = blockIdx.x * blockDim.x + threadIdx.x;
    if (i >= (Bsz * Hn) / 4) return;
    ((float4*)dst)[i] = ((const float4*)src)[i];
}

// ---------------------------------------------------------------------------
extern "C" void kernel_launch(void* const* d_in, const int* in_sizes, int n_in,
                              void* d_out, int out_size)
{
    const float* action      = (const float*)d_in[0];
    const float* prev_hidden = (const float*)d_in[1];
    const int*   gt          = (const int*)d_in[2];
    const float* W_a         = (const float*)d_in[3];
    const float* b_a         = (const float*)d_in[4];
    const float* emb         = (const float*)d_in[5];
    const float* W_tp        = (const float*)d_in[6];
    const float* b_tp        = (const float*)d_in[7];
    const float* W_ih        = (const float*)d_in[8];
    const float* W_hh        = (const float*)d_in[9];
    const float* b_ih        = (const float*)d_in[10];
    const float* b_hh        = (const float*)d_in[11];
    const float* W_out       = (const float*)d_in[12];
    const float* b_out       = (const float*)d_in[13];
    const float* W_r         = (const float*)d_in[14];
    const float* b_r         = (const float*)d_in[15];
    const float* W_d         = (const float*)d_in[16];
    const float* b_d         = (const float*)d_in[17];
    float* out = (float*)d_out;

    float *bufA, *bufB, *GI, *GH;
    cudaGetSymbolAddress((void**)&bufA, g_bufA);
    cudaGetSymbolAddress((void**)&bufB, g_bufB);
    cudaGetSymbolAddress((void**)&GI,   g_GI);
    cudaGetSymbolAddress((void**)&GH,   g_GH);

    const size_t BH  = (size_t)Bsz * Hn;    // 2,097,152
    const size_t BH3 = (size_t)Bsz * H3;

    // output layout: logits [B,G,G,C] | reward [B,1] | done [B,1] | final_hidden [L,B,H]
    float* outLogits = out;
    float* outReward = out + (size_t)Bsz * Tn * Cn;
    float* outDone   = outReward + Bsz;
    float* outFinal  = outDone + Bsz;

    // 1) build layer-0 input sequence: slot0 = x0, slot1 = zeros,
    //    slots 2..16 = proj(emb[gt[:, 0..14]])
    u0_kernel<<<(Bsz * Hn + 255) / 256, 256>>>(action, W_a, b_a, bufA);
    sgemm_nt<1><<<dim3(Hn / 128, (15 * Bsz) / 128), 256>>>(
        emb, W_tp, b_tp, bufA + 2 * BH, 15 * Bsz, Hn, Hn, gt);

    // 2) layer-by-layer GRU: batched input gates, then 17 sequential hidden steps
    float* U  = bufA;
    float* Ho = bufB;
    for (int l = 0; l < Ln; l++) {
        sgemm_nt<0><<<dim3(H3 / 128, (NSTEP * Bsz) / 128), 256>>>(
            U, W_ih + (size_t)l * H3 * Hn, b_ih + l * H3, GI,
            NSTEP * Bsz, H3, Hn, nullptr);
        for (int t = 0; t < NSTEP; t++) {
            const float* hp = (t == 0) ? (prev_hidden + (size_t)l * BH)
                                       : (Ho + (size_t)(t - 1) * BH);
            sgemm_nt<0><<<dim3(H3 / 128, Bsz / 128), 256>>>(
                hp, W_hh + (size_t)l * H3 * Hn, b_hh + l * H3, GH,
                Bsz, H3, Hn, nullptr);
            gru_gate_kernel<<<(Bsz * Hn + 255) / 256, 256>>>(
                GI + (size_t)t * BH3, GH, hp, Ho + (size_t)t * BH);
        }
        // final hidden of this layer (step 16) -> output, before buffer reuse
        copy_kernel<<<(Bsz * Hn / 4 + 255) / 256, 256>>>(
            Ho + (size_t)16 * BH, outFinal + (size_t)l * BH);
        float* tmp = U; U = Ho; Ho = tmp;
    }
    float* H2 = U;   // layer-2 output sequence (bufB)

    // 3) logits over scan steps 1..16: [T*B, C] GEMM with [B,T,C] scatter
    sgemm_nt<2><<<dim3(Cn / 128, (Tn * Bsz) / 128), 256>>>(
        H2 + BH, W_out, b_out, outLogits, Tn * Bsz, Cn, Hn, nullptr);

    // 4) reward / done heads from h_trans[-1] = layer-2 output at step 0
    heads_kernel<<<(Bsz * 32 + 255) / 256, 256>>>(
        H2, W_r, b_r, W_d, b_d, outReward, outDone);
}

// round 3
// speedup vs baseline: 2.0223x; 2.0223x over previous
#include <cuda_runtime.h>
#include <cuda_bf16.h>
#include <cstdint>
#include <math.h>

// ---------------- problem constants ----------------
#define Bsz   4096
#define Hn    512
#define H3    1536
#define Ln    3
#define Tn    16
#define Cn    512
#define NSTEP 17
#define KDIM  512
#define NCHUNK 8           // K chunks of 64 bf16 (128B rows)

static const size_t BH  = (size_t)Bsz * Hn;    // 2,097,152
static const size_t BH3 = (size_t)Bsz * H3;    // 6,291,456

// ---------------- persistent device scratch ----------------
__device__ __align__(128) __nv_bfloat16 g_seqA_hi[(size_t)NSTEP * Bsz * Hn];
__device__ __align__(128) __nv_bfloat16 g_seqA_lo[(size_t)NSTEP * Bsz * Hn];
__device__ __align__(128) __nv_bfloat16 g_seqB_hi[(size_t)NSTEP * Bsz * Hn];
__device__ __align__(128) __nv_bfloat16 g_seqB_lo[(size_t)NSTEP * Bsz * Hn];
__device__ __align__(128) float         g_hseqF[(size_t)NSTEP * Bsz * Hn];
__device__ __align__(128) float         g_GI[(size_t)NSTEP * Bsz * H3];
__device__ __align__(128) float         g_GH[(size_t)Bsz * H3];
__device__ __align__(128) __nv_bfloat16 g_prevH_hi[(size_t)Ln * Bsz * Hn];
__device__ __align__(128) __nv_bfloat16 g_prevH_lo[(size_t)Ln * Bsz * Hn];
__device__ __align__(128) __nv_bfloat16 g_Wih_hi[(size_t)Ln * H3 * Hn];
__device__ __align__(128) __nv_bfloat16 g_Wih_lo[(size_t)Ln * H3 * Hn];
__device__ __align__(128) __nv_bfloat16 g_Whh_hi[(size_t)Ln * H3 * Hn];
__device__ __align__(128) __nv_bfloat16 g_Whh_lo[(size_t)Ln * H3 * Hn];
__device__ __align__(128) __nv_bfloat16 g_Wout_hi[(size_t)Cn * Hn];
__device__ __align__(128) __nv_bfloat16 g_Wout_lo[(size_t)Cn * Hn];
__device__ __align__(128) __nv_bfloat16 g_Wtp_hi[(size_t)Hn * Hn];
__device__ __align__(128) __nv_bfloat16 g_Wtp_lo[(size_t)Hn * Hn];
__device__ __align__(128) __nv_bfloat16 g_emb_hi[(size_t)Cn * Hn];
__device__ __align__(128) __nv_bfloat16 g_emb_lo[(size_t)Cn * Hn];
__device__ __align__(128) float         g_P[(size_t)Cn * Hn];   // proj table [token, H]

// ---------------- PTX helpers (baseline features only, no 'a'-suffix) ------
__device__ __forceinline__ uint32_t smem_u32(const void* p) {
    uint32_t a;
    asm("{ .reg .u64 t; cvta.to.shared.u64 t, %1; cvt.u32.u64 %0, t; }" : "=r"(a) : "l"(p));
    return a;
}
__device__ __forceinline__ void cpasync16(uint32_t s, const void* g) {
    asm volatile("cp.async.cg.shared.global [%0], [%1], 16;" :: "r"(s), "l"(g));
}
__device__ __forceinline__ void cp_commit() {
    asm volatile("cp.async.commit_group;" ::: "memory");
}
template <int N> __device__ __forceinline__ void cp_wait() {
    asm volatile("cp.async.wait_group %0;" :: "n"(N) : "memory");
}
__device__ __forceinline__ void ldsm4(uint32_t& r0, uint32_t& r1, uint32_t& r2, uint32_t& r3,
                                      uint32_t addr) {
    asm volatile("ldmatrix.sync.aligned.m8n8.x4.shared.b16 {%0,%1,%2,%3}, [%4];"
                 : "=r"(r0), "=r"(r1), "=r"(r2), "=r"(r3) : "r"(addr));
}
__device__ __forceinline__ void mma16816(float* d, const uint32_t* a, uint32_t b0, uint32_t b1) {
    asm volatile(
        "mma.sync.aligned.m16n8k16.row.col.f32.bf16.bf16.f32 "
        "{%0,%1,%2,%3}, {%4,%5,%6,%7}, {%8,%9}, {%0,%1,%2,%3};"
        : "+f"(d[0]), "+f"(d[1]), "+f"(d[2]), "+f"(d[3])
        : "r"(a[0]), "r"(a[1]), "r"(a[2]), "r"(a[3]), "r"(b0), "r"(b1));
}

#define GEMM_SMEM (2 * 65536)   // 2 stages x (4 plane-tiles x 16KB)

// ---------------------------------------------------------------------------
// bf16x3 tensor-core GEMM: C[m,n] = sum_k (Ah+Al)[m,k]*(Bh+Bl)[n,k] + bias[n]
//   = Ah.Bh + Ah.Bl + Al.Bh  (fp32 accumulate)
// A planes [M,512], B planes [N,512], both bf16 row-major (K contiguous).
// 128x128 CTA tile, BK=64, cp.async double buffer, 8 warps (4x2), warp 32x64.
// MODE 0: row-major C (ld=ldc). MODE 2: logits scatter [B,T,C].
// ---------------------------------------------------------------------------
template <int MODE>
__global__ void __launch_bounds__(256)
gemm_bf16x3(const __nv_bfloat16* __restrict__ Ahi, const __nv_bfloat16* __restrict__ Alo,
            const __nv_bfloat16* __restrict__ Bhi, const __nv_bfloat16* __restrict__ Blo,
            const float* __restrict__ bias, float* __restrict__ C, int ldc)
{
    extern __shared__ __align__(128) char smem[];
    const uint32_t sb = smem_u32(smem);
    const int tid  = threadIdx.x;
    const int wid  = tid >> 5, lane = tid & 31;
    const int wM   = wid >> 1;             // 0..3  (m offset 32 each)
    const int wN   = wid & 1;              // 0..1  (n offset 64 each)
    const int m0   = blockIdx.y << 7, n0 = blockIdx.x << 7;

    const char* gAh = (const char*)(Ahi + (size_t)m0 * KDIM);
    const char* gAl = (const char*)(Alo + (size_t)m0 * KDIM);
    const char* gBh = (const char*)(Bhi + (size_t)n0 * KDIM);
    const char* gBl = (const char*)(Blo + (size_t)n0 * KDIM);

    // per-thread cp.async segment coords (4 segments of 16B per plane per chunk)
    int srow[4], soff[4]; uint32_t sso[4];
#pragma unroll
    for (int q = 0; q < 4; q++) {
        int id = tid * 4 + q;              // 0..1023
        srow[q] = id >> 3;
        soff[q] = (id & 7) << 4;
        sso[q]  = (uint32_t)((srow[q] << 7) | (soff[q] ^ ((srow[q] & 7) << 4)));
    }

    // ldmatrix row/base precompute
    const int lr16 = lane & 15;            // row within 16-row tile
    const int lhi  = (lane >> 4) << 4;     // 0 or 16: k-halve byte offset
    // A: two m-tiles per warp
    uint32_t aBase[2];
#pragma unroll
    for (int mt = 0; mt < 2; mt++) {
        int r = wM * 32 + mt * 16 + lr16;
        aBase[mt] = (uint32_t)(r << 7) | 0x80000000u;  // marker removed below
        aBase[mt] = (uint32_t)(r << 7);
    }
    const uint32_t aXr0 = (((wM * 32 + 0  + lr16) & 7) << 4);
    const uint32_t aXr1 = (((wM * 32 + 16 + lr16) & 7) << 4);
    // B: four n16-tiles per warp
    uint32_t bBase[4], bXr[4];
#pragma unroll
    for (int nt = 0; nt < 4; nt++) {
        int r = wN * 64 + nt * 16 + lr16;
        bBase[nt] = (uint32_t)(r << 7);
        bXr[nt]   = ((r & 7) << 4);
    }

    float acc[2][8][4];
#pragma unroll
    for (int i = 0; i < 2; i++)
#pragma unroll
        for (int j = 0; j < 8; j++)
#pragma unroll
            for (int v = 0; v < 4; v++) acc[i][j][v] = 0.f;

    auto load_chunk = [&](int s, int c) {
        const uint32_t st = sb + s * 65536;
        const int cb = c * 128;
#pragma unroll
        for (int q = 0; q < 4; q++) {
            int go = srow[q] * 1024 + cb + soff[q];
            cpasync16(st +         sso[q], gAh + go);
            cpasync16(st + 16384 + sso[q], gAl + go);
            cpasync16(st + 32768 + sso[q], gBh + go);
            cpasync16(st + 49152 + sso[q], gBl + go);
        }
        cp_commit();
    };

    load_chunk(0, 0);

    for (int c = 0; c < NCHUNK; c++) {
        const int s = c & 1;
        if (c + 1 < NCHUNK) { load_chunk(s ^ 1, c + 1); cp_wait<1>(); }
        else                { cp_wait<0>(); }
        __syncthreads();

        const uint32_t stA0 = sb + s * 65536;           // Ah
        const uint32_t stA1 = stA0 + 16384;             // Al
        const uint32_t stB0 = stA0 + 32768;             // Bh
        const uint32_t stB1 = stA0 + 49152;             // Bl

#pragma unroll
        for (int k16 = 0; k16 < 4; k16++) {
            const uint32_t ko = (uint32_t)(k16 * 32 + lhi);
            uint32_t ah[2][4], al[2][4];
            ldsm4(ah[0][0], ah[0][1], ah[0][2], ah[0][3], stA0 + aBase[0] + (ko ^ aXr0));
            ldsm4(ah[1][0], ah[1][1], ah[1][2], ah[1][3], stA0 + aBase[1] + (ko ^ aXr1));
            ldsm4(al[0][0], al[0][1], al[0][2], al[0][3], stA1 + aBase[0] + (ko ^ aXr0));
            ldsm4(al[1][0], al[1][1], al[1][2], al[1][3], stA1 + aBase[1] + (ko ^ aXr1));
            uint32_t bh[4][4], bl[4][4];
#pragma unroll
            for (int nt = 0; nt < 4; nt++) {
                ldsm4(bh[nt][0], bh[nt][1], bh[nt][2], bh[nt][3],
                      stB0 + bBase[nt] + (ko ^ bXr[nt]));
                ldsm4(bl[nt][0], bl[nt][1], bl[nt][2], bl[nt][3],
                      stB1 + bBase[nt] + (ko ^ bXr[nt]));
            }
#pragma unroll
            for (int mt = 0; mt < 2; mt++)
#pragma unroll
                for (int nt = 0; nt < 4; nt++) {
                    // frag (n0-7) = (r0,r2); frag (n8-15) = (r1,r3)
                    mma16816(acc[mt][2 * nt + 0], ah[mt], bh[nt][0], bh[nt][2]);
                    mma16816(acc[mt][2 * nt + 1], ah[mt], bh[nt][1], bh[nt][3]);
                    mma16816(acc[mt][2 * nt + 0], ah[mt], bl[nt][0], bl[nt][2]);
                    mma16816(acc[mt][2 * nt + 1], ah[mt], bl[nt][1], bl[nt][3]);
                    mma16816(acc[mt][2 * nt + 0], al[mt], bh[nt][0], bh[nt][2]);
                    mma16816(acc[mt][2 * nt + 1], al[mt], bh[nt][1], bh[nt][3]);
                }
        }
        __syncthreads();
    }

    // ---- epilogue: bias add + store ----
    const int lr = lane >> 2;          // 0..7
    const int lc = (lane & 3) << 1;    // 0,2,4,6
#pragma unroll
    for (int mt = 0; mt < 2; mt++) {
        const int mBase = m0 + wM * 32 + mt * 16 + lr;
#pragma unroll
        for (int nt = 0; nt < 8; nt++) {
            const int n = n0 + wN * 64 + nt * 8 + lc;
            const float b0 = bias[n], b1 = bias[n + 1];
            float2 v0 = make_float2(acc[mt][nt][0] + b0, acc[mt][nt][1] + b1);
            float2 v1 = make_float2(acc[mt][nt][2] + b0, acc[mt][nt][3] + b1);
            size_t o0, o1;
            if (MODE == 2) {
                int bb0 = mBase & (Bsz - 1),      t0 = mBase >> 12;
                int bb1 = (mBase + 8) & (Bsz - 1), t1 = (mBase + 8) >> 12;
                o0 = (size_t)bb0 * (Tn * Cn) + (size_t)t0 * Cn + n;
                o1 = (size_t)bb1 * (Tn * Cn) + (size_t)t1 * Cn + n;
            } else {
                o0 = (size_t)mBase * ldc + n;
                o1 = (size_t)(mBase + 8) * ldc + n;
            }
            *(float2*)(C + o0) = v0;
            *(float2*)(C + o1) = v1;
        }
    }
}

// ---------------- elementwise kernels ----------------
__device__ __forceinline__ void split1(float x, __nv_bfloat16& h, __nv_bfloat16& l) {
    h = __float2bfloat16(x);
    l = __float2bfloat16(x - __bfloat162float(h));
}

__global__ void split_kernel(const float* __restrict__ src,
                             __nv_bfloat16* __restrict__ hi,
                             __nv_bfloat16* __restrict__ lo, int n4)
{
    int i = blockIdx.x * blockDim.x + threadIdx.x;
    if (i >= n4) return;
    float4 v = ((const float4*)src)[i];
    __nv_bfloat16 h0, h1, h2, h3, l0, l1, l2, l3;
    split1(v.x, h0, l0); split1(v.y, h1, l1); split1(v.z, h2, l2); split1(v.w, h3, l3);
    ((__nv_bfloat162*)hi)[2 * i + 0] = __nv_bfloat162{h0, h1};
    ((__nv_bfloat162*)hi)[2 * i + 1] = __nv_bfloat162{h2, h3};
    ((__nv_bfloat162*)lo)[2 * i + 0] = __nv_bfloat162{l0, l1};
    ((__nv_bfloat162*)lo)[2 * i + 1] = __nv_bfloat162{l2, l3};
}

// x0 planes (slot0) + zero planes (slot1)
__global__ void u0_kernel(const float* __restrict__ action, const float* __restrict__ W_a,
                          const float* __restrict__ b_a,
                          __nv_bfloat16* __restrict__ hi, __nv_bfloat16* __restrict__ lo)
{
    int i = blockIdx.x * blockDim.x + threadIdx.x;
    if (i >= Bsz * Hn) return;
    int b = i >> 9, j = i & 511;
    float s = b_a[j];
    s = fmaf(action[b * 3 + 0], W_a[j * 3 + 0], s);
    s = fmaf(action[b * 3 + 1], W_a[j * 3 + 1], s);
    s = fmaf(action[b * 3 + 2], W_a[j * 3 + 2], s);
    __nv_bfloat16 h, l;
    split1(s, h, l);
    hi[i] = h; lo[i] = l;
    __nv_bfloat16 z = __float2bfloat16(0.f);
    hi[BH + i] = z; lo[BH + i] = z;
}

// gather projected-embedding rows into slots 2..16
__global__ void gatherP_kernel(const float* __restrict__ P, const int* __restrict__ gt,
                               __nv_bfloat16* __restrict__ hi, __nv_bfloat16* __restrict__ lo)
{
    int i = blockIdx.x * blockDim.x + threadIdx.x;   // over 15*B*(H/4)
    if (i >= 15 * Bsz * (Hn / 4)) return;
    int j4  = (i & 127) << 2;
    int row = i >> 7;
    int b   = row & (Bsz - 1);
    int s   = row >> 12;                              // 0..14
    int tok = gt[b * Tn + s];
    float4 v = *(const float4*)(P + (size_t)tok * Hn + j4);
    __nv_bfloat16 h0, h1, h2, h3, l0, l1, l2, l3;
    split1(v.x, h0, l0); split1(v.y, h1, l1); split1(v.z, h2, l2); split1(v.w, h3, l3);
    size_t o = (size_t)(2 + s) * BH + (size_t)b * Hn + j4;
    *(__nv_bfloat162*)(hi + o)     = __nv_bfloat162{h0, h1};
    *(__nv_bfloat162*)(hi + o + 2) = __nv_bfloat162{h2, h3};
    *(__nv_bfloat162*)(lo + o)     = __nv_bfloat162{l0, l1};
    *(__nv_bfloat162*)(lo + o + 2) = __nv_bfloat162{l2, l3};
}

__device__ __forceinline__ float sigf(float x) { return 1.f / (1.f + __expf(-x)); }

// GRU gate: h' = (1-z)*n + z*h  (fp32 state + bf16 planes out)
__global__ void gate_kernel(const float* __restrict__ GIt, const float* __restrict__ GH,
                            const float* __restrict__ hprev, float* __restrict__ houtF,
                            __nv_bfloat16* __restrict__ hi, __nv_bfloat16* __restrict__ lo)
{
    int i = blockIdx.x * blockDim.x + threadIdx.x;   // over B*H/2
    if (i >= Bsz * Hn / 2) return;
    int b  = i >> 8;
    int j2 = (i & 255) << 1;
    size_t o  = (size_t)b * H3 + j2;
    size_t ih = (size_t)b * Hn + j2;
    float2 gir = *(const float2*)(GIt + o);
    float2 giz = *(const float2*)(GIt + o + 512);
    float2 gin = *(const float2*)(GIt + o + 1024);
    float2 ghr = *(const float2*)(GH + o);
    float2 ghz = *(const float2*)(GH + o + 512);
    float2 ghn = *(const float2*)(GH + o + 1024);
    float2 hp  = *(const float2*)(hprev + ih);
    float rx = sigf(gir.x + ghr.x), ry = sigf(gir.y + ghr.y);
    float zx = sigf(giz.x + ghz.x), zy = sigf(giz.y + ghz.y);
    float nx = tanhf(gin.x + rx * ghn.x), ny = tanhf(gin.y + ry * ghn.y);
    float hx = (1.f - zx) * nx + zx * hp.x;
    float hy = (1.f - zy) * ny + zy * hp.y;
    *(float2*)(houtF + ih) = float2{hx, hy};
    __nv_bfloat16 hh0, hh1, ll0, ll1;
    split1(hx, hh0, ll0); split1(hy, hh1, ll1);
    *(__nv_bfloat162*)(hi + ih) = __nv_bfloat162{hh0, hh1};
    *(__nv_bfloat162*)(lo + ih) = __nv_bfloat162{ll0, ll1};
}

__global__ void copyf4_kernel(const float* __restrict__ src, float* __restrict__ dst)
{
    int i = blockIdx.x * blockDim.x + threadIdx.x;
    if (i >= (int)(BH / 4)) return;
    ((float4*)dst)[i] = ((const float4*)src)[i];
}

__global__ void heads_kernel(const float* __restrict__ h2, const float* __restrict__ W_r,
                             const float* __restrict__ b_r, const float* __restrict__ W_d,
                             const float* __restrict__ b_d,
                             float* __restrict__ outr, float* __restrict__ outd)
{
    int gw = (blockIdx.x * blockDim.x + threadIdx.x) >> 5;
    int lane = threadIdx.x & 31;
    if (gw >= Bsz) return;
    const float* hb = h2 + (size_t)gw * Hn;
    float sr = 0.f, sd = 0.f;
#pragma unroll
    for (int k = lane; k < Hn; k += 32) {
        float v = hb[k];
        sr = fmaf(v, W_r[k], sr);
        sd = fmaf(v, W_d[k], sd);
    }
#pragma unroll
    for (int o = 16; o > 0; o >>= 1) {
        sr += __shfl_down_sync(0xffffffffu, sr, o);
        sd += __shfl_down_sync(0xffffffffu, sd, o);
    }
    if (lane == 0) { outr[gw] = sr + b_r[0]; outd[gw] = sd + b_d[0]; }
}

// ---------------------------------------------------------------------------
extern "C" void kernel_launch(void* const* d_in, const int* in_sizes, int n_in,
                              void* d_out, int out_size)
{
    const float* action      = (const float*)d_in[0];
    const float* prev_hidden = (const float*)d_in[1];
    const int*   gt          = (const int*)d_in[2];
    const float* W_a         = (const float*)d_in[3];
    const float* b_a         = (const float*)d_in[4];
    const float* emb         = (const float*)d_in[5];
    const float* W_tp        = (const float*)d_in[6];
    const float* b_tp        = (const float*)d_in[7];
    const float* W_ih        = (const float*)d_in[8];
    const float* W_hh        = (const float*)d_in[9];
    const float* b_ih        = (const float*)d_in[10];
    const float* b_hh        = (const float*)d_in[11];
    const float* W_out       = (const float*)d_in[12];
    const float* b_out       = (const float*)d_in[13];
    const float* W_r         = (const float*)d_in[14];
    const float* b_r         = (const float*)d_in[15];
    const float* W_d         = (const float*)d_in[16];
    const float* b_d         = (const float*)d_in[17];
    float* out = (float*)d_out;

    static bool attr_done = false;
    if (!attr_done) {
        cudaFuncSetAttribute(gemm_bf16x3<0>, cudaFuncAttributeMaxDynamicSharedMemorySize, GEMM_SMEM);
        cudaFuncSetAttribute(gemm_bf16x3<2>, cudaFuncAttributeMaxDynamicSharedMemorySize, GEMM_SMEM);
        attr_done = true;
    }

    __nv_bfloat16 *seqAh, *seqAl, *seqBh, *seqBl, *pHh, *pHl;
    __nv_bfloat16 *wihH, *wihL, *whhH, *whhL, *woH, *woL, *wtH, *wtL, *emH, *emL;
    float *hseqF, *GI, *GH, *P;
    cudaGetSymbolAddress((void**)&seqAh, g_seqA_hi);
    cudaGetSymbolAddress((void**)&seqAl, g_seqA_lo);
    cudaGetSymbolAddress((void**)&seqBh, g_seqB_hi);
    cudaGetSymbolAddress((void**)&seqBl, g_seqB_lo);
    cudaGetSymbolAddress((void**)&pHh,   g_prevH_hi);
    cudaGetSymbolAddress((void**)&pHl,   g_prevH_lo);
    cudaGetSymbolAddress((void**)&wihH,  g_Wih_hi);
    cudaGetSymbolAddress((void**)&wihL,  g_Wih_lo);
    cudaGetSymbolAddress((void**)&whhH,  g_Whh_hi);
    cudaGetSymbolAddress((void**)&whhL,  g_Whh_lo);
    cudaGetSymbolAddress((void**)&woH,   g_Wout_hi);
    cudaGetSymbolAddress((void**)&woL,   g_Wout_lo);
    cudaGetSymbolAddress((void**)&wtH,   g_Wtp_hi);
    cudaGetSymbolAddress((void**)&wtL,   g_Wtp_lo);
    cudaGetSymbolAddress((void**)&emH,   g_emb_hi);
    cudaGetSymbolAddress((void**)&emL,   g_emb_lo);
    cudaGetSymbolAddress((void**)&hseqF, g_hseqF);
    cudaGetSymbolAddress((void**)&GI,    g_GI);
    cudaGetSymbolAddress((void**)&GH,    g_GH);
    cudaGetSymbolAddress((void**)&P,     g_P);

    float* outLogits = out;
    float* outReward = out + (size_t)Bsz * Tn * Cn;
    float* outDone   = outReward + Bsz;
    float* outFinal  = outDone + Bsz;

    // ---- conversions to bf16 hi/lo planes ----
    auto splitN = [&](const float* s, __nv_bfloat16* h, __nv_bfloat16* l, size_t n) {
        int n4 = (int)(n / 4);
        split_kernel<<<(n4 + 255) / 256, 256>>>(s, h, l, n4);
    };
    splitN(W_ih, wihH, wihL, (size_t)Ln * H3 * Hn);
    splitN(W_hh, whhH, whhL, (size_t)Ln * H3 * Hn);
    splitN(W_out, woH, woL, (size_t)Cn * Hn);
    splitN(W_tp, wtH, wtL, (size_t)Hn * Hn);
    splitN(emb, emH, emL, (size_t)Cn * Hn);
    splitN(prev_hidden, pHh, pHl, (size_t)Ln * Bsz * Hn);

    // ---- projection table: P[token,h] = emb[token] . W_tp[h] + b_tp ----
    gemm_bf16x3<0><<<dim3(Hn / 128, Cn / 128), 256, GEMM_SMEM>>>(
        emH, emL, wtH, wtL, b_tp, P, Hn);

    // ---- layer-0 input sequence planes ----
    u0_kernel<<<(Bsz * Hn + 255) / 256, 256>>>(action, W_a, b_a, seqAh, seqAl);
    gatherP_kernel<<<(15 * Bsz * (Hn / 4) + 255) / 256, 256>>>(P, gt, seqAh, seqAl);

    // ---- 3 GRU layers ----
    __nv_bfloat16 *Uh = seqAh, *Ul = seqAl, *Oh = seqBh, *Ol = seqBl;
    for (int l = 0; l < Ln; l++) {
        gemm_bf16x3<0><<<dim3(H3 / 128, (NSTEP * Bsz) / 128), 256, GEMM_SMEM>>>(
            Uh, Ul, wihH + (size_t)l * H3 * Hn, wihL + (size_t)l * H3 * Hn,
            b_ih + l * H3, GI, H3);
        for (int t = 0; t < NSTEP; t++) {
            const __nv_bfloat16* ph = t ? (Oh + (size_t)(t - 1) * BH) : (pHh + (size_t)l * BH);
            const __nv_bfloat16* pl = t ? (Ol + (size_t)(t - 1) * BH) : (pHl + (size_t)l * BH);
            gemm_bf16x3<0><<<dim3(H3 / 128, Bsz / 128), 256, GEMM_SMEM>>>(
                ph, pl, whhH + (size_t)l * H3 * Hn, whhL + (size_t)l * H3 * Hn,
                b_hh + l * H3, GH, H3);
            const float* hpF = t ? (hseqF + (size_t)(t - 1) * BH)
                                 : (prev_hidden + (size_t)l * BH);
            gate_kernel<<<(Bsz * Hn / 2 + 255) / 256, 256>>>(
                GI + (size_t)t * BH3, GH, hpF, hseqF + (size_t)t * BH,
                Oh + (size_t)t * BH, Ol + (size_t)t * BH);
        }
        copyf4_kernel<<<((int)(BH / 4) + 255) / 256, 256>>>(
            hseqF + (size_t)16 * BH, outFinal + (size_t)l * BH);
        __nv_bfloat16* tmp;
        tmp = Uh; Uh = Oh; Oh = tmp;
        tmp = Ul; Ul = Ol; Ol = tmp;
    }

    // ---- logits over scan slots 1..16 (layer-2 output planes) ----
    gemm_bf16x3<2><<<dim3(Cn / 128, (Tn * Bsz) / 128), 256, GEMM_SMEM>>>(
        Uh + BH, Ul + BH, woH, woL, b_out, outLogits, 0);

    // ---- reward / done heads from layer-2 fp32 state at slot 0 ----
    heads_kernel<<<(Bsz * 32 + 255) / 256, 256>>>(
        hseqF, W_r, b_r, W_d, b_d, outReward, outDone);
}